// round 12
// baseline (speedup 1.0000x reference)
#include <cuda_runtime.h>

#define BB 4
#define LL 256
#define DD 256

// scratch (allocation-free contract: __device__ globals, zero-initialized)
__device__ float g_Sdep[BB * LL * DD];  // 1 MB : sum_j adj * dep
__device__ float g_S0[BB * LL * DD];    // 1 MB : adj @ text
__device__ float g_A[BB * LL];          // row sums of adj
__device__ float g_Wt[DD * DD];         // W transposed: Wt[d*256 + o]

// dataflow sync state (must be 0 at every launch; last out-performer resets)
__device__ int g_tilecnt[128];               // dep rows done per out tile
__device__ volatile int g_s0flag[128];       // per-tile "S0 ready"
__device__ volatile int g_wtcnt;             // transpose blocks done (32)
__device__ int g_outcnt;                     // out tiles done (128)

// ---- packed f32x2 helpers (Blackwell FFMA2) --------------------------------
__device__ __forceinline__ unsigned long long splat2(float s) {
    unsigned long long r;
    asm("mov.b64 %0, {%1, %1};" : "=l"(r) : "f"(s));
    return r;
}
__device__ __forceinline__ void fma2(unsigned long long& acc,
                                     unsigned long long a,
                                     unsigned long long b) {
    asm("fma.rn.f32x2 %0, %1, %2, %0;" : "+l"(acc) : "l"(a), "l"(b));
}
__device__ __forceinline__ void unpk2(float& lo, float& hi, unsigned long long v) {
    asm("mov.b64 {%0, %1}, %2;" : "=f"(lo), "=f"(hi) : "l"(v));
}

// smem layout (union across roles); max user = out stage
#define OFF_SS    0        // Ssm [8][264] floats = 8448 B (also adjs/red/tile)
#define OFF_WTS   8448     // Wts [2][16][64] float4 = 32768 B
#define OFF_AA    41216    // A [8] floats
#define OFF_DEC   41248    // int: "this block performs out"
#define OFF_LASTF 41252    // int
#define SMEM_SZ   41280

// ---------------------------------------------------------------------------
// k_mega: ONE kernel, grid 1184 x 256, zero spinner blocks.
//   bx in [0,32)     : W transpose -> g_Wt (2 tiles each), wtcnt++
//   bx in [32,160)   : S0 tile [8 rows] = adj@text + A -> global, s0flag
//   bx in [160,1184) : dep row; the 8th finisher of each 8-row tile then
//                      performs that tile's out GEMM inline (work stealing).
// ---------------------------------------------------------------------------
__global__ void __launch_bounds__(256, 4)
k_mega(const float* __restrict__ text,
       const float* __restrict__ adj,
       const float* __restrict__ dep,
       const float* __restrict__ W,
       const float* __restrict__ bias,
       float* __restrict__ out) {
    const int bx = blockIdx.x;
    const int t  = threadIdx.x;

    __shared__ __align__(16) char smraw[SMEM_SZ];

    // =========================== transpose role ===========================
    if (bx < 32) {
        float (*tile)[33] = (float (*)[33])smraw;
        const int tx = t & 31, ty = t >> 5;   // (32, 8)
#pragma unroll 1
        for (int pass = 0; pass < 2; pass++) {
            const int bb = bx + pass * 32;
            const int d0 = (bb & 7) * 32, o0 = (bb >> 3) * 32;
#pragma unroll
            for (int k = 0; k < 32; k += 8)
                tile[ty + k][tx] = W[(o0 + ty + k) * DD + (d0 + tx)];
            __syncthreads();
#pragma unroll
            for (int k = 0; k < 32; k += 8)
                g_Wt[(d0 + ty + k) * DD + (o0 + tx)] = tile[tx][ty + k];
            __syncthreads();
        }
        __threadfence();
        __syncthreads();
        if (t == 0) atomicAdd((int*)&g_wtcnt, 1);
        return;
    }

    // ============================ S0 gemm role =============================
    if (bx < 160) {
        const int g    = bx - 32;          // tile id 0..127
        const int row0 = g * 8;            // global row = b*256 + i
        const int b    = row0 >> 8;

        float (*adjs)[LL] = (float (*)[LL])smraw;
        const float* adjg = adj + (size_t)row0 * LL;
#pragma unroll
        for (int r = 0; r < 8; r++) adjs[r][t] = adjg[r * LL + t];
        __syncthreads();

        {   // A row sums: warp w reduces adjs[w]
            const int warp = t >> 5, lane = t & 31;
            float s = 0.f;
#pragma unroll
            for (int k = 0; k < 8; k++) s += adjs[warp][lane + 32 * k];
#pragma unroll
            for (int off = 16; off; off >>= 1)
                s += __shfl_xor_sync(0xffffffffu, s, off);
            if (lane == 0) g_A[row0 + warp] = s;
        }

        const int o4 = t & 63;
        const int rg = t >> 6;
        const int r0 = rg * 2, r1 = r0 + 1;

        const float4* text4 = (const float4*)text + ((size_t)b * LL << 6) + o4;
        float4 acc0 = make_float4(0.f, 0.f, 0.f, 0.f);
        float4 acc1 = make_float4(0.f, 0.f, 0.f, 0.f);

#pragma unroll 1
        for (int j = 0; j < LL; j += 4) {
            float4 tv[4];
#pragma unroll
            for (int u = 0; u < 4; u++) tv[u] = text4[(j + u) << 6];
#pragma unroll
            for (int u = 0; u < 4; u++) {
                const float a0 = adjs[r0][j + u];
                const float a1 = adjs[r1][j + u];
                acc0.x += a0 * tv[u].x;  acc0.y += a0 * tv[u].y;
                acc0.z += a0 * tv[u].z;  acc0.w += a0 * tv[u].w;
                acc1.x += a1 * tv[u].x;  acc1.y += a1 * tv[u].y;
                acc1.z += a1 * tv[u].z;  acc1.w += a1 * tv[u].w;
            }
        }
        ((float4*)g_S0)[((row0 + r0) << 6) + o4] = acc0;
        ((float4*)g_S0)[((row0 + r1) << 6) + o4] = acc1;

        __threadfence();
        __syncthreads();
        if (t == 0) g_s0flag[g] = 1;
        return;
    }

    // ============================= dep role ===============================
    const int id = bx - 160;          // global row = b*256 + i
    {
        const int b  = id >> 8;
        const int i  = id & 255;
        const int jj = t >> 6;
        const int d4 = t & 63;

        float*  adjs1 = (float*)smraw;                  // [256]
        float4* red   = (float4*)(smraw + 1024);        // [4][64]

        adjs1[t] = adj[(b * LL + i) * LL + t];
        __syncthreads();

        const int jbase = jj << 6;
        const float4* p = (const float4*)dep
                        + (((size_t)(b * LL + jbase) * LL + i) << 6) + d4;
        const size_t jstride = (size_t)LL << 6;   // 16384 float4 per j

        float4 acc = make_float4(0.f, 0.f, 0.f, 0.f);

#pragma unroll 1
        for (int js = 0; js < 64; js += 8) {
            float4 dv[8];
#pragma unroll
            for (int u = 0; u < 8; u++)
                dv[u] = __ldcs(p + (size_t)u * jstride);   // 8 LDG.128 in flight
            p += jstride * 8;
#pragma unroll
            for (int u = 0; u < 8; u++) {
                const float a = adjs1[jbase + js + u];
                acc.x += a * dv[u].x;
                acc.y += a * dv[u].y;
                acc.z += a * dv[u].z;
                acc.w += a * dv[u].w;
            }
        }

        red[(jj << 6) + d4] = acc;
        __syncthreads();
        if (t < 64) {
            float4 r0 = red[t], r1 = red[64 + t], r2 = red[128 + t], r3 = red[192 + t];
            float4 s;
            s.x = (r0.x + r1.x) + (r2.x + r3.x);
            s.y = (r0.y + r1.y) + (r2.y + r3.y);
            s.z = (r0.z + r1.z) + (r2.z + r3.z);
            s.w = (r0.w + r1.w) + (r2.w + r3.w);
            ((float4*)g_Sdep)[(id << 6) + t] = s;
        }
        __threadfence();      // release: Sdep row visible before counter bump
        __syncthreads();
    }

    // ---- tile counter: 8th finisher performs the out GEMM ----
    int* dec = (int*)(smraw + OFF_DEC);
    const int tile = id >> 3;
    if (t == 0) *dec = (atomicAdd(&g_tilecnt[tile], 1) == 7) ? 1 : 0;
    __syncthreads();
    if (!*dec) return;

    // ============================== out role ===============================
    const int row0 = tile * 8;

    if (t == 0) {
        while (g_wtcnt < 32) __nanosleep(64);
        while (g_s0flag[tile] == 0) __nanosleep(64);
    }
    __syncthreads();
    __threadfence();   // acquire: order reads after counter/flag observation

    float* Ss = (float*)smraw;                        // [8][264]
    float* Aa = (float*)(smraw + OFF_AA);             // [8]
    int*   lastf = (int*)(smraw + OFF_LASTF);

    // ---- stage S = S0 + Sdep (8 rows, padded stride 264) + A ----
    {
        const float4* S0g = (const float4*)(g_S0   + (size_t)row0 * DD);
        const float4* Sdg = (const float4*)(g_Sdep + (size_t)row0 * DD);
#pragma unroll
        for (int k = 0; k < 2; k++) {
            const int idx = t + 256 * k;
            const int rr = idx >> 6, cc = idx & 63;
            float4 a = S0g[idx];
            float4 c = Sdg[idx];
            a.x += c.x; a.y += c.y; a.z += c.z; a.w += c.w;
            *(float4*)&Ss[rr * 264 + (cc << 2)] = a;
        }
        if (t < 8) Aa[t] = g_A[row0 + t];
    }
    __syncthreads();

    // ---- out compute: 8 rows x 256 cols, double-buffered smem Wt + FFMA2 ----
    {
        float4 (*Wts)[16][64] = (float4 (*)[16][64])(smraw + OFF_WTS);
        const int c4 = t & 63;
        const int rh = t >> 6;
        const int rr0 = rh * 2, rr1 = rr0 + 1;
        const float4* Wtg = (const float4*)g_Wt;

        float4 pre[4];
#pragma unroll
        for (int k = 0; k < 4; k++)
            pre[k] = Wtg[((rh + 4 * k) << 6) + c4];

        unsigned long long aL0 = 0ull, aH0 = 0ull, aL1 = 0ull, aH1 = 0ull;

#pragma unroll 1
        for (int ch = 0; ch < 16; ch++) {
            const int buf = ch & 1;
#pragma unroll
            for (int k = 0; k < 4; k++)
                Wts[buf][rh + 4 * k][c4] = pre[k];
            __syncthreads();

            if (ch < 15) {
                const int dbase = (ch + 1) * 16;
#pragma unroll
                for (int k = 0; k < 4; k++)
                    pre[k] = Wtg[((dbase + rh + 4 * k) << 6) + c4];
            }

            const int dc = ch * 16;
#pragma unroll
            for (int d = 0; d < 16; d++) {
                const ulonglong2 w = *(const ulonglong2*)&Wts[buf][d][c4];
                const unsigned long long sp0 = splat2(Ss[rr0 * 264 + dc + d]);
                const unsigned long long sp1 = splat2(Ss[rr1 * 264 + dc + d]);
                fma2(aL0, w.x, sp0);  fma2(aH0, w.y, sp0);
                fma2(aL1, w.x, sp1);  fma2(aH1, w.y, sp1);
            }
            __syncthreads();
        }

        float4 res0, res1;
        unpk2(res0.x, res0.y, aL0);  unpk2(res0.z, res0.w, aH0);
        unpk2(res1.x, res1.y, aL1);  unpk2(res1.z, res1.w, aH1);

        const float4 bi = ((const float4*)bias)[c4];
        const float  a0 = Aa[rr0];
        const float  a1 = Aa[rr1];
        res0.x += a0 * bi.x;  res0.y += a0 * bi.y;
        res0.z += a0 * bi.z;  res0.w += a0 * bi.w;
        res1.x += a1 * bi.x;  res1.y += a1 * bi.y;
        res1.z += a1 * bi.z;  res1.w += a1 * bi.w;

        ((float4*)(out + (size_t)(row0 + rr0) * DD))[c4] = res0;
        ((float4*)(out + (size_t)(row0 + rr1) * DD))[c4] = res1;
    }

    // ---- last out-performer resets all sync state for the next replay ----
    __syncthreads();
    if (t == 0) *lastf = (atomicAdd(&g_outcnt, 1) == 127) ? 1 : 0;
    __syncthreads();
    if (*lastf) {
        if (t < 128) { g_tilecnt[t] = 0; g_s0flag[t] = 0; }
        if (t == 0)  { g_wtcnt = 0; g_outcnt = 0; }
    }
}

// ---------------------------------------------------------------------------
extern "C" void kernel_launch(void* const* d_in, const int* in_sizes, int n_in,
                              void* d_out, int out_size) {
    const float* text = (const float*)d_in[0];  // [4,256,256]
    const float* adj  = (const float*)d_in[1];  // [4,256,256]
    const float* dep  = (const float*)d_in[2];  // [4,256,256,256]
    const float* W    = (const float*)d_in[3];  // [256,256]
    const float* bias = (const float*)d_in[4];  // [256]
    float* out = (float*)d_out;                 // [4,256,256]

    k_mega<<<160 + BB * LL, 256>>>(text, adj, dep, W, bias, out);
}

// round 13
// speedup vs baseline: 1.0577x; 1.0577x over previous
#include <cuda_runtime.h>

#define BB 4
#define LL 256
#define DD 256

// scratch (allocation-free contract: __device__ globals, zero-initialized)
__device__ float g_Sdep[BB * LL * DD];  // 1 MB : sum_j adj * dep
__device__ float g_Wt[DD * DD];         // W transposed: Wt[d*256 + o]

// dataflow sync state (must be 0 at every launch; last out block resets)
__device__ volatile int g_depflag[BB * LL];  // per-row "Sdep row ready"
__device__ volatile int g_wtcnt;             // transpose blocks done (32)
__device__ int g_outcnt;                     // out blocks done (128)

// smem layout (union across roles); lean: 8.5 KB total
#define OFF_SS    0        // Ssm [8][264] floats = 8448 B (also adjs/red)
#define OFF_AA    8448     // A [8] floats
#define OFF_LASTF 8480     // int
#define SMEM_SZ   8512

// ---------------------------------------------------------------------------
// k_mega: ONE kernel, grid 1184 x 256 (r11 structure, lean resources).
//   bx in [0,128)    : S0 gemm into smem -> wait(Wt, own 8 dep rows)
//                      -> S += Sdep -> out GEMM (direct Wt stream, MLP=4)
//   bx in [128,160)  : W transpose -> g_Wt (2 tiles each), wtcnt++
//   bx in [160,1184) : dep row (b,i): Sdep = sum_j adj*dep  (DRAM stream)
// __launch_bounds__(256,6): regs <= 42 -> ~6 blocks/SM resident -> enough
// in-flight LDG bytes to approach the DRAM roofline during the stream.
// ---------------------------------------------------------------------------
__global__ void __launch_bounds__(256, 6)
k_mega(const float* __restrict__ text,
       const float* __restrict__ adj,
       const float* __restrict__ dep,
       const float* __restrict__ W,
       const float* __restrict__ bias,
       float* __restrict__ out) {
    const int bx = blockIdx.x;
    const int t  = threadIdx.x;

    __shared__ __align__(16) char smraw[SMEM_SZ];

    // =========================== transpose role ===========================
    if (bx >= 128 && bx < 160) {
        float (*tile)[33] = (float (*)[33])smraw;
        const int tx = t & 31, ty = t >> 5;   // (32, 8)
#pragma unroll 1
        for (int pass = 0; pass < 2; pass++) {
            const int bb = (bx - 128) + pass * 32;
            const int d0 = (bb & 7) * 32, o0 = (bb >> 3) * 32;
#pragma unroll
            for (int k = 0; k < 32; k += 8)
                tile[ty + k][tx] = W[(o0 + ty + k) * DD + (d0 + tx)];
            __syncthreads();
#pragma unroll
            for (int k = 0; k < 32; k += 8)
                g_Wt[(d0 + ty + k) * DD + (o0 + tx)] = tile[tx][ty + k];
            __syncthreads();
        }
        __threadfence();
        __syncthreads();
        if (t == 0) atomicAdd((int*)&g_wtcnt, 1);
        return;
    }

    // ============================= dep role ===============================
    if (bx >= 160) {
        const int id = bx - 160;          // global row = b*256 + i
        const int b  = id >> 8;
        const int i  = id & 255;
        const int jj = t >> 6;
        const int d4 = t & 63;

        float*  adjs1 = (float*)smraw;                  // [256]
        float4* red   = (float4*)(smraw + 1024);        // [4][64]

        adjs1[t] = adj[(b * LL + i) * LL + t];
        __syncthreads();

        const int jbase = jj << 6;
        const float4* p = (const float4*)dep
                        + (((size_t)(b * LL + jbase) * LL + i) << 6) + d4;
        const size_t jstride = (size_t)LL << 6;   // 16384 float4 per j

        float4 acc = make_float4(0.f, 0.f, 0.f, 0.f);

#pragma unroll 1
        for (int js = 0; js < 64; js += 8) {
            float4 dv[8];
#pragma unroll
            for (int u = 0; u < 8; u++)
                dv[u] = __ldcs(p + (size_t)u * jstride);   // 8 LDG.128 in flight
            p += jstride * 8;
#pragma unroll
            for (int u = 0; u < 8; u++) {
                const float a = adjs1[jbase + js + u];
                acc.x += a * dv[u].x;
                acc.y += a * dv[u].y;
                acc.z += a * dv[u].z;
                acc.w += a * dv[u].w;
            }
        }

        red[(jj << 6) + d4] = acc;
        __syncthreads();
        if (t < 64) {
            float4 r0 = red[t], r1 = red[64 + t], r2 = red[128 + t], r3 = red[192 + t];
            float4 s;
            s.x = (r0.x + r1.x) + (r2.x + r3.x);
            s.y = (r0.y + r1.y) + (r2.y + r3.y);
            s.z = (r0.z + r1.z) + (r2.z + r3.z);
            s.w = (r0.w + r1.w) + (r2.w + r3.w);
            ((float4*)g_Sdep)[(id << 6) + t] = s;
        }
        __threadfence();      // release: Sdep row visible before flag
        __syncthreads();
        if (t == 0) g_depflag[id] = 1;
        return;
    }

    // ================== combined gemm -> wait -> out role ==================
    const int row0 = bx * 8;              // global rows row0..row0+7
    const int b    = row0 >> 8;

    float* Ss = (float*)smraw;                        // [8][264] after gemm
    float* Aa = (float*)(smraw + OFF_AA);             // [8]
    int*   lastf = (int*)(smraw + OFF_LASTF);

    {   // ---- S0 = adj @ text (8 rows) -> smem, A -> smem ----
        float (*adjs)[LL] = (float (*)[LL])smraw;
        const float* adjg = adj + (size_t)row0 * LL;
#pragma unroll
        for (int r = 0; r < 8; r++) adjs[r][t] = adjg[r * LL + t];
        __syncthreads();

        {   // A row sums: warp w reduces adjs[w]
            const int warp = t >> 5, lane = t & 31;
            float s = 0.f;
#pragma unroll
            for (int k = 0; k < 8; k++) s += adjs[warp][lane + 32 * k];
#pragma unroll
            for (int off = 16; off; off >>= 1)
                s += __shfl_xor_sync(0xffffffffu, s, off);
            if (lane == 0) Aa[warp] = s;
        }

        const int o4 = t & 63;
        const int rg = t >> 6;
        const int r0 = rg * 2, r1 = r0 + 1;

        const float4* text4 = (const float4*)text + ((size_t)b * LL << 6) + o4;
        float4 acc0 = make_float4(0.f, 0.f, 0.f, 0.f);
        float4 acc1 = make_float4(0.f, 0.f, 0.f, 0.f);

#pragma unroll 1
        for (int j = 0; j < LL; j += 4) {
            float4 tv[4];
#pragma unroll
            for (int u = 0; u < 4; u++) tv[u] = text4[(j + u) << 6];
#pragma unroll
            for (int u = 0; u < 4; u++) {
                const float a0 = adjs[r0][j + u];
                const float a1 = adjs[r1][j + u];
                acc0.x += a0 * tv[u].x;  acc0.y += a0 * tv[u].y;
                acc0.z += a0 * tv[u].z;  acc0.w += a0 * tv[u].w;
                acc1.x += a1 * tv[u].x;  acc1.y += a1 * tv[u].y;
                acc1.z += a1 * tv[u].z;  acc1.w += a1 * tv[u].w;
            }
        }
        __syncthreads();   // all adjs reads done; safe to overwrite with Ssm
        *(float4*)&Ss[r0 * 264 + (o4 << 2)] = acc0;
        *(float4*)&Ss[r1 * 264 + (o4 << 2)] = acc1;
    }

    // ---- wait for Wt (32 transpose blocks) and our 8 Sdep rows ----
    if (t == 0) {
        while (g_wtcnt < 32) __nanosleep(128);
#pragma unroll 1
        for (int r = 0; r < 8; r++)
            while (g_depflag[row0 + r] == 0) __nanosleep(128);
    }
    __syncthreads();
    __threadfence();   // acquire: order subsequent reads after flag observation

    // ---- S += Sdep (8 rows) ----
    {
        const float4* Sdg = (const float4*)(g_Sdep + (size_t)row0 * DD);
#pragma unroll
        for (int k = 0; k < 2; k++) {
            const int idx = t + 256 * k;
            const int rr = idx >> 6, cc = idx & 63;
            float4 c = Sdg[idx];
            float4* pp = (float4*)&Ss[rr * 264 + (cc << 2)];
            float4 a = *pp;
            a.x += c.x; a.y += c.y; a.z += c.z; a.w += c.w;
            *pp = a;
        }
    }
    __syncthreads();

    // ---- out compute: 8 rows x 256 cols, lean direct Wt stream (MLP=4) ----
    // thread: c4 = t&63 (float4 col), rh = t>>6 -> rows rh*2, rh*2+1
    // s reads are warp-uniform smem broadcasts; plain C++ FMA so ptxas
    // front-batches the 4 independent LDG.128 per iteration.
    {
        const int c4 = t & 63;
        const int rh = t >> 6;
        const int rr0 = rh * 2, rr1 = rr0 + 1;
        const float* S0r = &Ss[rr0 * 264];
        const float* S1r = &Ss[rr1 * 264];

        const float4* Wtg = (const float4*)g_Wt + c4;
        float4 acc0 = make_float4(0.f, 0.f, 0.f, 0.f);
        float4 acc1 = make_float4(0.f, 0.f, 0.f, 0.f);

#pragma unroll 1
        for (int d = 0; d < DD; d += 4) {
            float4 wv[4];
#pragma unroll
            for (int k = 0; k < 4; k++)
                wv[k] = Wtg[(d + k) << 6];          // 4 independent LDG.128
#pragma unroll
            for (int k = 0; k < 4; k++) {
                const float s0 = S0r[d + k];
                const float s1 = S1r[d + k];
                acc0.x += s0 * wv[k].x;  acc0.y += s0 * wv[k].y;
                acc0.z += s0 * wv[k].z;  acc0.w += s0 * wv[k].w;
                acc1.x += s1 * wv[k].x;  acc1.y += s1 * wv[k].y;
                acc1.z += s1 * wv[k].z;  acc1.w += s1 * wv[k].w;
            }
        }

        const float4 bi = ((const float4*)bias)[c4];
        const float  a0 = Aa[rr0];
        const float  a1 = Aa[rr1];
        acc0.x += a0 * bi.x;  acc0.y += a0 * bi.y;
        acc0.z += a0 * bi.z;  acc0.w += a0 * bi.w;
        acc1.x += a1 * bi.x;  acc1.y += a1 * bi.y;
        acc1.z += a1 * bi.z;  acc1.w += a1 * bi.w;

        ((float4*)(out + (size_t)(row0 + rr0) * DD))[c4] = acc0;
        ((float4*)(out + (size_t)(row0 + rr1) * DD))[c4] = acc1;
    }

    // ---- last out block resets all sync state for the next graph replay ----
    __syncthreads();
    if (t == 0) *lastf = (atomicAdd(&g_outcnt, 1) == 127) ? 1 : 0;
    __syncthreads();
    if (*lastf) {
        for (int i = t; i < BB * LL; i += 256) g_depflag[i] = 0;
        if (t == 0) { g_wtcnt = 0; g_outcnt = 0; }
    }
}

// ---------------------------------------------------------------------------
extern "C" void kernel_launch(void* const* d_in, const int* in_sizes, int n_in,
                              void* d_out, int out_size) {
    const float* text = (const float*)d_in[0];  // [4,256,256]
    const float* adj  = (const float*)d_in[1];  // [4,256,256]
    const float* dep  = (const float*)d_in[2];  // [4,256,256,256]
    const float* W    = (const float*)d_in[3];  // [256,256]
    const float* bias = (const float*)d_in[4];  // [256]
    float* out = (float*)d_out;                 // [4,256,256]

    k_mega<<<160 + BB * LL, 256>>>(text, adj, dep, W, bias, out);
}

// round 14
// speedup vs baseline: 1.1566x; 1.0934x over previous
#include <cuda_runtime.h>

#define BB 4
#define LL 256
#define DD 256

// scratch (allocation-free contract: __device__ globals, zero-initialized)
__device__ float g_Sdep[BB * LL * DD];  // 1 MB : sum_j adj * dep
__device__ float g_S0[BB * LL * DD];    // 1 MB : adj @ text
__device__ float g_A[BB * LL];          // row sums of adj
__device__ float g_Wt[DD * DD];         // W transposed: Wt[d*256 + o]

// dataflow sync state (must be 0 at every launch; last out block resets)
__device__ volatile int g_depflag[BB * LL];  // per-row "Sdep row ready"
__device__ volatile int g_s0flag[128];       // per-tile "S0 ready"
__device__ volatile int g_wtcnt;             // transpose blocks done (32)
__device__ int g_outcnt;                     // out blocks done (128)

// ---- packed f32x2 helpers (Blackwell FFMA2) --------------------------------
__device__ __forceinline__ unsigned long long splat2(float s) {
    unsigned long long r;
    asm("mov.b64 %0, {%1, %1};" : "=l"(r) : "f"(s));
    return r;
}
__device__ __forceinline__ void fma2(unsigned long long& acc,
                                     unsigned long long a,
                                     unsigned long long b) {
    asm("fma.rn.f32x2 %0, %1, %2, %0;" : "+l"(acc) : "l"(a), "l"(b));
}
__device__ __forceinline__ void unpk2(float& lo, float& hi, unsigned long long v) {
    asm("mov.b64 {%0, %1}, %2;" : "=f"(lo), "=f"(hi) : "l"(v));
}

// smem layout (union across roles); max user = out stage
#define OFF_SS    0        // Ssm [8][264] floats = 8448 B (also adjs/red/tile)
#define OFF_WTS   8448     // Wts [2][16][64] float4 = 32768 B
#define OFF_AA    41216    // A [8] floats
#define OFF_LASTF 41248    // int
#define SMEM_SZ   41280

// ---------------------------------------------------------------------------
// k_mega: ONE kernel, grid 1312 x 256. Producers first, FAST out last:
//   bx in [0,32)       : W transpose -> g_Wt (2 tiles each), wtcnt++
//   bx in [32,160)     : S0 tile [8 rows] = adj@text + A -> global, s0flag
//   bx in [160,1184)   : dep row (b,i): Sdep = sum_j adj*dep (DRAM stream)
//   bx in [1184,1312)  : out tile [8 rows x 256]: wait flags -> double-
//                        buffered smem-Wt FFMA2 GEMM (proven ~5us/block).
// During the stream NO waiters squat (producers retire fast; out blocks are
// scheduled only as dep blocks retire, and their flags are already set).
// All waits target lower-bid never-waiting blocks -> deadlock-free.
// ---------------------------------------------------------------------------
__global__ void __launch_bounds__(256, 4)
k_mega(const float* __restrict__ text,
       const float* __restrict__ adj,
       const float* __restrict__ dep,
       const float* __restrict__ W,
       const float* __restrict__ bias,
       float* __restrict__ out) {
    const int bx = blockIdx.x;
    const int t  = threadIdx.x;

    __shared__ __align__(16) char smraw[SMEM_SZ];

    // =========================== transpose role ===========================
    if (bx < 32) {
        float (*tile)[33] = (float (*)[33])smraw;
        const int tx = t & 31, ty = t >> 5;   // (32, 8)
#pragma unroll 1
        for (int pass = 0; pass < 2; pass++) {
            const int bb = bx + pass * 32;
            const int d0 = (bb & 7) * 32, o0 = (bb >> 3) * 32;
#pragma unroll
            for (int k = 0; k < 32; k += 8)
                tile[ty + k][tx] = W[(o0 + ty + k) * DD + (d0 + tx)];
            __syncthreads();
#pragma unroll
            for (int k = 0; k < 32; k += 8)
                g_Wt[(d0 + ty + k) * DD + (o0 + tx)] = tile[tx][ty + k];
            __syncthreads();
        }
        __threadfence();
        __syncthreads();
        if (t == 0) atomicAdd((int*)&g_wtcnt, 1);
        return;
    }

    // ============================ S0 gemm role =============================
    if (bx < 160) {
        const int g    = bx - 32;          // tile id 0..127
        const int row0 = g * 8;            // global row = b*256 + i
        const int b    = row0 >> 8;

        float (*adjs)[LL] = (float (*)[LL])smraw;
        const float* adjg = adj + (size_t)row0 * LL;
#pragma unroll
        for (int r = 0; r < 8; r++) adjs[r][t] = adjg[r * LL + t];
        __syncthreads();

        {   // A row sums: warp w reduces adjs[w]
            const int warp = t >> 5, lane = t & 31;
            float s = 0.f;
#pragma unroll
            for (int k = 0; k < 8; k++) s += adjs[warp][lane + 32 * k];
#pragma unroll
            for (int off = 16; off; off >>= 1)
                s += __shfl_xor_sync(0xffffffffu, s, off);
            if (lane == 0) g_A[row0 + warp] = s;
        }

        const int o4 = t & 63;
        const int rg = t >> 6;
        const int r0 = rg * 2, r1 = r0 + 1;

        const float4* text4 = (const float4*)text + ((size_t)b * LL << 6) + o4;
        float4 acc0 = make_float4(0.f, 0.f, 0.f, 0.f);
        float4 acc1 = make_float4(0.f, 0.f, 0.f, 0.f);

#pragma unroll 1
        for (int j = 0; j < LL; j += 4) {
            float4 tv[4];
#pragma unroll
            for (int u = 0; u < 4; u++) tv[u] = text4[(j + u) << 6];
#pragma unroll
            for (int u = 0; u < 4; u++) {
                const float a0 = adjs[r0][j + u];
                const float a1 = adjs[r1][j + u];
                acc0.x += a0 * tv[u].x;  acc0.y += a0 * tv[u].y;
                acc0.z += a0 * tv[u].z;  acc0.w += a0 * tv[u].w;
                acc1.x += a1 * tv[u].x;  acc1.y += a1 * tv[u].y;
                acc1.z += a1 * tv[u].z;  acc1.w += a1 * tv[u].w;
            }
        }
        ((float4*)g_S0)[((row0 + r0) << 6) + o4] = acc0;
        ((float4*)g_S0)[((row0 + r1) << 6) + o4] = acc1;

        __threadfence();
        __syncthreads();
        if (t == 0) g_s0flag[g] = 1;
        return;
    }

    // ============================= dep role ===============================
    if (bx < 1184) {
        const int id = bx - 160;          // global row = b*256 + i
        const int b  = id >> 8;
        const int i  = id & 255;
        const int jj = t >> 6;
        const int d4 = t & 63;

        float*  adjs1 = (float*)smraw;                  // [256]
        float4* red   = (float4*)(smraw + 1024);        // [4][64]

        adjs1[t] = adj[(b * LL + i) * LL + t];
        __syncthreads();

        const int jbase = jj << 6;
        const float4* p = (const float4*)dep
                        + (((size_t)(b * LL + jbase) * LL + i) << 6) + d4;
        const size_t jstride = (size_t)LL << 6;   // 16384 float4 per j

        float4 acc = make_float4(0.f, 0.f, 0.f, 0.f);

#pragma unroll 1
        for (int js = 0; js < 64; js += 8) {
            float4 dv[8];
#pragma unroll
            for (int u = 0; u < 8; u++)
                dv[u] = __ldcs(p + (size_t)u * jstride);   // 8 LDG.128 in flight
            p += jstride * 8;
#pragma unroll
            for (int u = 0; u < 8; u++) {
                const float a = adjs1[jbase + js + u];
                acc.x += a * dv[u].x;
                acc.y += a * dv[u].y;
                acc.z += a * dv[u].z;
                acc.w += a * dv[u].w;
            }
        }

        red[(jj << 6) + d4] = acc;
        __syncthreads();
        if (t < 64) {
            float4 r0 = red[t], r1 = red[64 + t], r2 = red[128 + t], r3 = red[192 + t];
            float4 s;
            s.x = (r0.x + r1.x) + (r2.x + r3.x);
            s.y = (r0.y + r1.y) + (r2.y + r3.y);
            s.z = (r0.z + r1.z) + (r2.z + r3.z);
            s.w = (r0.w + r1.w) + (r2.w + r3.w);
            ((float4*)g_Sdep)[(id << 6) + t] = s;
        }
        __threadfence();      // release: Sdep row visible before flag
        __syncthreads();
        if (t == 0) g_depflag[id] = 1;
        return;
    }

    // ============================== out role ===============================
    const int tile = bx - 1184;           // tile id 0..127
    const int row0 = tile * 8;

    // ---- wait for Wt, our S0 tile, and our 8 Sdep rows (usually instant) ----
    if (t == 0) {
        while (g_wtcnt < 32) __nanosleep(64);
        while (g_s0flag[tile] == 0) __nanosleep(64);
#pragma unroll 1
        for (int r = 0; r < 8; r++)
            while (g_depflag[row0 + r] == 0) __nanosleep(64);
    }
    __syncthreads();
    __threadfence();   // acquire: order reads after flag observation

    float* Ss = (float*)smraw;                        // [8][264]
    float* Aa = (float*)(smraw + OFF_AA);             // [8]
    int*   lastf = (int*)(smraw + OFF_LASTF);

    // ---- stage S = S0 + Sdep (8 rows, padded stride 264) + A ----
    {
        const float4* S0g = (const float4*)(g_S0   + (size_t)row0 * DD);
        const float4* Sdg = (const float4*)(g_Sdep + (size_t)row0 * DD);
#pragma unroll
        for (int k = 0; k < 2; k++) {
            const int idx = t + 256 * k;
            const int rr = idx >> 6, cc = idx & 63;
            float4 a = S0g[idx];
            float4 c = Sdg[idx];
            a.x += c.x; a.y += c.y; a.z += c.z; a.w += c.w;
            *(float4*)&Ss[rr * 264 + (cc << 2)] = a;
        }
        if (t < 8) Aa[t] = g_A[row0 + t];
    }
    __syncthreads();

    // ---- out compute: 8 rows x 256 cols, double-buffered smem Wt + FFMA2 ----
    {
        float4 (*Wts)[16][64] = (float4 (*)[16][64])(smraw + OFF_WTS);
        const int c4 = t & 63;
        const int rh = t >> 6;
        const int rr0 = rh * 2, rr1 = rr0 + 1;
        const float4* Wtg = (const float4*)g_Wt;

        float4 pre[4];
#pragma unroll
        for (int k = 0; k < 4; k++)
            pre[k] = Wtg[((rh + 4 * k) << 6) + c4];

        unsigned long long aL0 = 0ull, aH0 = 0ull, aL1 = 0ull, aH1 = 0ull;

#pragma unroll 1
        for (int ch = 0; ch < 16; ch++) {
            const int buf = ch & 1;
#pragma unroll
            for (int k = 0; k < 4; k++)
                Wts[buf][rh + 4 * k][c4] = pre[k];
            __syncthreads();

            if (ch < 15) {
                const int dbase = (ch + 1) * 16;
#pragma unroll
                for (int k = 0; k < 4; k++)
                    pre[k] = Wtg[((dbase + rh + 4 * k) << 6) + c4];
            }

            const int dc = ch * 16;
#pragma unroll
            for (int d = 0; d < 16; d++) {
                const ulonglong2 w = *(const ulonglong2*)&Wts[buf][d][c4];
                const unsigned long long sp0 = splat2(Ss[rr0 * 264 + dc + d]);
                const unsigned long long sp1 = splat2(Ss[rr1 * 264 + dc + d]);
                fma2(aL0, w.x, sp0);  fma2(aH0, w.y, sp0);
                fma2(aL1, w.x, sp1);  fma2(aH1, w.y, sp1);
            }
            __syncthreads();
        }

        float4 res0, res1;
        unpk2(res0.x, res0.y, aL0);  unpk2(res0.z, res0.w, aH0);
        unpk2(res1.x, res1.y, aL1);  unpk2(res1.z, res1.w, aH1);

        const float4 bi = ((const float4*)bias)[c4];
        const float  a0 = Aa[rr0];
        const float  a1 = Aa[rr1];
        res0.x += a0 * bi.x;  res0.y += a0 * bi.y;
        res0.z += a0 * bi.z;  res0.w += a0 * bi.w;
        res1.x += a1 * bi.x;  res1.y += a1 * bi.y;
        res1.z += a1 * bi.z;  res1.w += a1 * bi.w;

        ((float4*)(out + (size_t)(row0 + rr0) * DD))[c4] = res0;
        ((float4*)(out + (size_t)(row0 + rr1) * DD))[c4] = res1;
    }

    // ---- last out block resets all sync state for the next graph replay ----
    __syncthreads();
    if (t == 0) *lastf = (atomicAdd(&g_outcnt, 1) == 127) ? 1 : 0;
    __syncthreads();
    if (*lastf) {
        for (int i = t; i < BB * LL; i += 256) g_depflag[i] = 0;
        if (t < 128) g_s0flag[t] = 0;
        if (t == 0)  { g_wtcnt = 0; g_outcnt = 0; }
    }
}

// ---------------------------------------------------------------------------
extern "C" void kernel_launch(void* const* d_in, const int* in_sizes, int n_in,
                              void* d_out, int out_size) {
    const float* text = (const float*)d_in[0];  // [4,256,256]
    const float* adj  = (const float*)d_in[1];  // [4,256,256]
    const float* dep  = (const float*)d_in[2];  // [4,256,256,256]
    const float* W    = (const float*)d_in[3];  // [256,256]
    const float* bias = (const float*)d_in[4];  // [256]
    float* out = (float*)d_out;                 // [4,256,256]

    k_mega<<<1312, 256>>>(text, adj, dep, W, bias, out);
}

// round 15
// speedup vs baseline: 1.2431x; 1.0748x over previous
#include <cuda_runtime.h>

#define BB 4
#define LL 256
#define DD 256

// scratch (allocation-free contract: __device__ globals, zero-initialized)
__device__ float g_SdepA[BB * LL * DD];  // partial: j in [0,128)
__device__ float g_SdepB[BB * LL * DD];  // partial: j in [128,256)
__device__ float g_Wt[DD * DD];          // W transposed: Wt[d*256 + o]

// dataflow sync state (must be 0 at every launch; last out block resets)
__device__ volatile int g_depcnt[BB * LL];   // halves done per row (==2 ready)
__device__ volatile int g_wtcnt;             // transpose blocks done (32)
__device__ int g_outcnt;                     // out blocks done (128)

// ---- packed f32x2 helpers (Blackwell FFMA2) --------------------------------
__device__ __forceinline__ unsigned long long splat2(float s) {
    unsigned long long r;
    asm("mov.b64 %0, {%1, %1};" : "=l"(r) : "f"(s));
    return r;
}
__device__ __forceinline__ void fma2(unsigned long long& acc,
                                     unsigned long long a,
                                     unsigned long long b) {
    asm("fma.rn.f32x2 %0, %1, %2, %0;" : "+l"(acc) : "l"(a), "l"(b));
}
__device__ __forceinline__ void unpk2(float& lo, float& hi, unsigned long long v) {
    asm("mov.b64 {%0, %1}, %2;" : "=f"(lo), "=f"(hi) : "l"(v));
}

// smem layout (union across roles); max user = out stage
#define OFF_SS    0        // Ssm [8][264] floats = 8448 B (also adjs/red)
#define OFF_WTS   8448     // Wts [2][16][64] float4 = 32768 B
#define OFF_AA    41216    // A [8] floats
#define OFF_LASTF 41248    // int
#define SMEM_SZ   41280

// ---------------------------------------------------------------------------
// k_mega: ONE kernel, grid 2208 x 256 (r11 champion structure + half-row dep).
//   bx in [0,128)    : S0 gemm into smem -> wait(Wt, own 8 rows cnt==2)
//                      -> S = S0 + SdA + SdB -> out GEMM (dbuf smem Wt, FFMA2)
//   bx in [128,160)  : W transpose -> g_Wt (2 tiles each), wtcnt++
//   bx in [160,2208) : dep HALF-row: e=bx-160, row=e>>1, half=e&1;
//                      partial Sdep over 128 j's -> g_Sdep{A,B}, depcnt[row]++
// Half-row quanta (~8.7us vs 17.5us) pack the DRAM stream tighter and halve
// the straggler tail each out tile waits on.
// ---------------------------------------------------------------------------
__global__ void __launch_bounds__(256, 4)
k_mega(const float* __restrict__ text,
       const float* __restrict__ adj,
       const float* __restrict__ dep,
       const float* __restrict__ W,
       const float* __restrict__ bias,
       float* __restrict__ out) {
    const int bx = blockIdx.x;
    const int t  = threadIdx.x;

    __shared__ __align__(16) char smraw[SMEM_SZ];

    // =========================== transpose role ===========================
    if (bx >= 128 && bx < 160) {
        float (*tile)[33] = (float (*)[33])smraw;
        const int tx = t & 31, ty = t >> 5;   // (32, 8)
#pragma unroll 1
        for (int pass = 0; pass < 2; pass++) {
            const int bb = (bx - 128) + pass * 32;
            const int d0 = (bb & 7) * 32, o0 = (bb >> 3) * 32;
#pragma unroll
            for (int k = 0; k < 32; k += 8)
                tile[ty + k][tx] = W[(o0 + ty + k) * DD + (d0 + tx)];
            __syncthreads();
#pragma unroll
            for (int k = 0; k < 32; k += 8)
                g_Wt[(d0 + ty + k) * DD + (o0 + tx)] = tile[tx][ty + k];
            __syncthreads();
        }
        __threadfence();
        __syncthreads();
        if (t == 0) atomicAdd((int*)&g_wtcnt, 1);
        return;
    }

    // ========================== dep half-row role ==========================
    if (bx >= 160) {
        const int e    = bx - 160;        // 0..2047
        const int id   = e >> 1;          // global row = b*256 + i
        const int half = e & 1;
        const int b    = id >> 8;
        const int i    = id & 255;
        const int jj   = t >> 6;
        const int d4   = t & 63;

        float*  adjs1 = (float*)smraw;                  // [256]
        float4* red   = (float4*)(smraw + 1024);        // [4][64]

        adjs1[t] = adj[(b * LL + i) * LL + t];
        __syncthreads();

        const int jbase = half * 128 + jj * 32;   // 32 j's per warp-pair group
        const float4* p = (const float4*)dep
                        + (((size_t)(b * LL + jbase) * LL + i) << 6) + d4;
        const size_t jstride = (size_t)LL << 6;   // 16384 float4 per j

        float4 acc = make_float4(0.f, 0.f, 0.f, 0.f);

#pragma unroll 1
        for (int js = 0; js < 32; js += 8) {
            float4 dv[8];
#pragma unroll
            for (int u = 0; u < 8; u++)
                dv[u] = __ldcs(p + (size_t)u * jstride);   // 8 LDG.128 in flight
            p += jstride * 8;
#pragma unroll
            for (int u = 0; u < 8; u++) {
                const float a = adjs1[jbase + js + u];
                acc.x += a * dv[u].x;
                acc.y += a * dv[u].y;
                acc.z += a * dv[u].z;
                acc.w += a * dv[u].w;
            }
        }

        red[(jj << 6) + d4] = acc;
        __syncthreads();
        if (t < 64) {
            float4 r0 = red[t], r1 = red[64 + t], r2 = red[128 + t], r3 = red[192 + t];
            float4 s;
            s.x = (r0.x + r1.x) + (r2.x + r3.x);
            s.y = (r0.y + r1.y) + (r2.y + r3.y);
            s.z = (r0.z + r1.z) + (r2.z + r3.z);
            s.w = (r0.w + r1.w) + (r2.w + r3.w);
            float* dst = half ? g_SdepB : g_SdepA;
            ((float4*)dst)[(id << 6) + t] = s;
        }
        __threadfence();      // release: partial visible before counter bump
        __syncthreads();
        if (t == 0) atomicAdd((int*)&g_depcnt[id], 1);
        return;
    }

    // ================== combined gemm -> wait -> out role ==================
    const int row0 = bx * 8;              // global rows row0..row0+7
    const int b    = row0 >> 8;

    float* Ss = (float*)smraw;                        // [8][264] after gemm
    float* Aa = (float*)(smraw + OFF_AA);             // [8]
    int*   lastf = (int*)(smraw + OFF_LASTF);

    {   // ---- S0 = adj @ text (8 rows) -> smem, A -> smem ----
        float (*adjs)[LL] = (float (*)[LL])smraw;
        const float* adjg = adj + (size_t)row0 * LL;
#pragma unroll
        for (int r = 0; r < 8; r++) adjs[r][t] = adjg[r * LL + t];
        __syncthreads();

        {   // A row sums: warp w reduces adjs[w]
            const int warp = t >> 5, lane = t & 31;
            float s = 0.f;
#pragma unroll
            for (int k = 0; k < 8; k++) s += adjs[warp][lane + 32 * k];
#pragma unroll
            for (int off = 16; off; off >>= 1)
                s += __shfl_xor_sync(0xffffffffu, s, off);
            if (lane == 0) Aa[warp] = s;
        }

        const int o4 = t & 63;
        const int rg = t >> 6;
        const int r0 = rg * 2, r1 = r0 + 1;

        const float4* text4 = (const float4*)text + ((size_t)b * LL << 6) + o4;
        float4 acc0 = make_float4(0.f, 0.f, 0.f, 0.f);
        float4 acc1 = make_float4(0.f, 0.f, 0.f, 0.f);

#pragma unroll 1
        for (int j = 0; j < LL; j += 4) {
            float4 tv[4];
#pragma unroll
            for (int u = 0; u < 4; u++) tv[u] = text4[(j + u) << 6];
#pragma unroll
            for (int u = 0; u < 4; u++) {
                const float a0 = adjs[r0][j + u];
                const float a1 = adjs[r1][j + u];
                acc0.x += a0 * tv[u].x;  acc0.y += a0 * tv[u].y;
                acc0.z += a0 * tv[u].z;  acc0.w += a0 * tv[u].w;
                acc1.x += a1 * tv[u].x;  acc1.y += a1 * tv[u].y;
                acc1.z += a1 * tv[u].z;  acc1.w += a1 * tv[u].w;
            }
        }
        __syncthreads();   // all adjs reads done; safe to overwrite with Ssm
        *(float4*)&Ss[r0 * 264 + (o4 << 2)] = acc0;
        *(float4*)&Ss[r1 * 264 + (o4 << 2)] = acc1;
    }

    // ---- wait for Wt and both halves of our 8 rows ----
    if (t == 0) {
        while (g_wtcnt < 32) __nanosleep(128);
#pragma unroll 1
        for (int r = 0; r < 8; r++)
            while (g_depcnt[row0 + r] < 2) __nanosleep(128);
    }
    __syncthreads();
    __threadfence();   // acquire: order subsequent reads after flag observation

    // ---- S += SdepA + SdepB (8 rows) ----
    {
        const float4* Sa = (const float4*)(g_SdepA + (size_t)row0 * DD);
        const float4* Sb = (const float4*)(g_SdepB + (size_t)row0 * DD);
#pragma unroll
        for (int k = 0; k < 2; k++) {
            const int idx = t + 256 * k;
            const int rr = idx >> 6, cc = idx & 63;
            float4 ca = Sa[idx];
            float4 cb = Sb[idx];
            float4* pp = (float4*)&Ss[rr * 264 + (cc << 2)];
            float4 a = *pp;
            a.x += ca.x + cb.x;  a.y += ca.y + cb.y;
            a.z += ca.z + cb.z;  a.w += ca.w + cb.w;
            *pp = a;
        }
    }
    __syncthreads();

    // ---- out compute: 8 rows x 256 cols, double-buffered smem Wt + FFMA2 ----
    {
        float4 (*Wts)[16][64] = (float4 (*)[16][64])(smraw + OFF_WTS);
        const int c4 = t & 63;
        const int rh = t >> 6;
        const int rr0 = rh * 2, rr1 = rr0 + 1;
        const float4* Wtg = (const float4*)g_Wt;

        float4 pre[4];
#pragma unroll
        for (int k = 0; k < 4; k++)
            pre[k] = Wtg[((rh + 4 * k) << 6) + c4];

        unsigned long long aL0 = 0ull, aH0 = 0ull, aL1 = 0ull, aH1 = 0ull;

#pragma unroll 1
        for (int ch = 0; ch < 16; ch++) {
            const int buf = ch & 1;
#pragma unroll
            for (int k = 0; k < 4; k++)
                Wts[buf][rh + 4 * k][c4] = pre[k];
            __syncthreads();

            if (ch < 15) {
                const int dbase = (ch + 1) * 16;
#pragma unroll
                for (int k = 0; k < 4; k++)
                    pre[k] = Wtg[((dbase + rh + 4 * k) << 6) + c4];
            }

            const int dc = ch * 16;
#pragma unroll
            for (int d = 0; d < 16; d++) {
                const ulonglong2 w = *(const ulonglong2*)&Wts[buf][d][c4];
                const unsigned long long sp0 = splat2(Ss[rr0 * 264 + dc + d]);
                const unsigned long long sp1 = splat2(Ss[rr1 * 264 + dc + d]);
                fma2(aL0, w.x, sp0);  fma2(aH0, w.y, sp0);
                fma2(aL1, w.x, sp1);  fma2(aH1, w.y, sp1);
            }
            __syncthreads();
        }

        float4 res0, res1;
        unpk2(res0.x, res0.y, aL0);  unpk2(res0.z, res0.w, aH0);
        unpk2(res1.x, res1.y, aL1);  unpk2(res1.z, res1.w, aH1);

        const float4 bi = ((const float4*)bias)[c4];
        const float  a0 = Aa[rr0];
        const float  a1 = Aa[rr1];
        res0.x += a0 * bi.x;  res0.y += a0 * bi.y;
        res0.z += a0 * bi.z;  res0.w += a0 * bi.w;
        res1.x += a1 * bi.x;  res1.y += a1 * bi.y;
        res1.z += a1 * bi.z;  res1.w += a1 * bi.w;

        ((float4*)(out + (size_t)(row0 + rr0) * DD))[c4] = res0;
        ((float4*)(out + (size_t)(row0 + rr1) * DD))[c4] = res1;
    }

    // ---- last out block resets all sync state for the next graph replay ----
    __syncthreads();
    if (t == 0) *lastf = (atomicAdd(&g_outcnt, 1) == 127) ? 1 : 0;
    __syncthreads();
    if (*lastf) {
        for (int i = t; i < BB * LL; i += 256) g_depcnt[i] = 0;
        if (t == 0) { g_wtcnt = 0; g_outcnt = 0; }
    }
}

// ---------------------------------------------------------------------------
extern "C" void kernel_launch(void* const* d_in, const int* in_sizes, int n_in,
                              void* d_out, int out_size) {
    const float* text = (const float*)d_in[0];  // [4,256,256]
    const float* adj  = (const float*)d_in[1];  // [4,256,256]
    const float* dep  = (const float*)d_in[2];  // [4,256,256,256]
    const float* W    = (const float*)d_in[3];  // [256,256]
    const float* bias = (const float*)d_in[4];  // [256]
    float* out = (float*)d_out;                 // [4,256,256]

    k_mega<<<160 + 2 * BB * LL, 256>>>(text, adj, dep, W, bias, out);
}